// round 15
// baseline (speedup 1.0000x reference)
#include <cuda_runtime.h>
#include <cuda_fp16.h>
#include <math.h>

#define VOL   2097152              // 128^3
#define NB    4
#define S2D   16384                // 128*128 (z stride)

// Normalized 1-D Gaussian weights (sigma=1.6, 7 taps), sum = 1.
#define W0 0.25603832f   // center
#define W1 0.21061137f   // +-1
#define W2 0.11722290f   // +-2
#define W3 0.04414655f   // +-3

// Scratch (allocation-free contract: __device__ globals) — fp16 to halve
// the write+read traffic of the smooth->integrate handoff.
__device__ __half g_a [(size_t)NB * VOL];   // d   smoothed in x,y
__device__ __half g_b [(size_t)NB * VOL];   // |curl v| smoothed in x,y

#define TSY 32
#define LDY 38    // TSY + 6 (y halo rows)
#define NQB 34    // phase-B halo quads per row: gx in [-4, 132)
#define SIN 140   // s_in row stride (floats): 136 data + 4 pad (560B, 16B mult)

#define F4Z make_float4(0.f, 0.f, 0.f, 0.f)

// 7-tap x-conv of a 4-wide output quad from three f4 windows:
// a = values at ox-4.., b = ox.., c = ox+4..
__device__ __forceinline__ float4 xconv(float4 a, float4 b, float4 c) {
    float4 r;
    r.x = W0 * b.x + W1 * (a.w + b.y) + W2 * (a.z + b.z) + W3 * (a.y + b.w);
    r.y = W0 * b.y + W1 * (b.x + b.z) + W2 * (a.w + b.w) + W3 * (a.z + c.x);
    r.z = W0 * b.z + W1 * (b.y + b.w) + W2 * (b.x + c.x) + W3 * (a.w + c.y);
    r.w = W0 * b.w + W1 * (b.z + c.x) + W2 * (b.y + c.y) + W3 * (b.x + c.z);
    return r;
}

// y-pass: one output quad column x 4 rows from a 10-row register window,
// packed to fp16 (two half2 = one 8B store per quad).
// itm in [0,256): ox = (itm&31)*4, oy = (itm>>5)*4.
__device__ __forceinline__ void ypass_store(const float (*s_tmp)[128],
                                            __half* outp, int ty0, int itm) {
    int ox = (itm & 31) * 4;
    int oy = (itm >> 5) * 4;
    float4 t[10];
#pragma unroll
    for (int r = 0; r < 10; r++)
        t[r] = *(const float4*)&s_tmp[oy + r][ox];
#pragma unroll
    for (int j = 0; j < 4; j++) {
        float4 r4;
        r4.x = W0 * t[j+3].x + W1 * (t[j+2].x + t[j+4].x)
             + W2 * (t[j+1].x + t[j+5].x) + W3 * (t[j].x + t[j+6].x);
        r4.y = W0 * t[j+3].y + W1 * (t[j+2].y + t[j+4].y)
             + W2 * (t[j+1].y + t[j+5].y) + W3 * (t[j].y + t[j+6].y);
        r4.z = W0 * t[j+3].z + W1 * (t[j+2].z + t[j+4].z)
             + W2 * (t[j+1].z + t[j+5].z) + W3 * (t[j].z + t[j+6].z);
        r4.w = W0 * t[j+3].w + W1 * (t[j+2].w + t[j+4].w)
             + W2 * (t[j+1].w + t[j+5].w) + W3 * (t[j].w + t[j+6].w);
        union { __half2 h2[2]; uint2 u; } pk;
        pk.h2[0] = __floats2half2_rn(r4.x, r4.y);
        pk.h2[1] = __floats2half2_rn(r4.z, r4.w);
        *(uint2*)(outp + (ty0 + oy + j) * 128 + ox) = pk.u;
    }
}

// ---------------------------------------------------------------------------
// Fused kernel, full-width 128x32 tiles:
//   phase A: d -> x-conv DIRECTLY from global (no staging) -> s_tmp -> y-pass -> g_a
//   phase B: |curl v| halo -> s_in -> x-pass -> s_tmp -> y-pass -> g_b
// ---------------------------------------------------------------------------
__global__ __launch_bounds__(256)
void fused_smooth_kernel(const float* __restrict__ d,
                         const float* __restrict__ v) {
    int ty0 = blockIdx.x * TSY;
    int nz  = blockIdx.y;            // n*128 + z
    int n = nz >> 7, z = nz & 127;

    __shared__ __align__(16) float s_in [LDY][SIN];
    __shared__ __align__(16) float s_tmp[LDY][128];

    int tid = threadIdx.x;

    // ============ phase A : x-conv of d straight from global =============
    {
        const float* slice = d + (size_t)n * VOL + z * S2D;
        for (int i = tid; i < LDY * 32; i += 256) {
            int ly = i >> 5, qx = i & 31;
            int gy = ty0 + ly - 3, ox = qx * 4;
            float4 a = F4Z, b = F4Z, c = F4Z;
            if ((unsigned)gy < 128u) {
                const float* row = slice + gy * 128;
                if (qx >= 1)  a = *(const float4*)(row + ox - 4);
                b = *(const float4*)(row + ox);
                if (qx <= 30) c = *(const float4*)(row + ox + 4);
            }
            *(float4*)&s_tmp[ly][ox] = xconv(a, b, c);
        }
    }
    __syncthreads();

    // A y-pass (reads s_tmp only) — overlaps with phase-B halo (writes s_in)
    ypass_store(s_tmp, g_a + (size_t)n * VOL + z * S2D, ty0, tid);

    // ======================= phase B : |curl v| halo ======================
    {
        const float* pu = v + (size_t)(n * 3 + 0) * VOL + z * S2D;
        const float* pv = v + (size_t)(n * 3 + 1) * VOL + z * S2D;
        const float* pw = v + (size_t)(n * 3 + 2) * VOL + z * S2D;
        const int   dzo = (z < 127) ? S2D : -S2D;
        const float ez  = (z < 127) ? 1.f : -1.f;

        for (int i = tid; i < LDY * NQB; i += 256) {
            int ly = i / NQB, q = i - ly * NQB;
            int gy = ty0 + ly - 3, gx = q * 4 - 4;
            float4 val = F4Z;
            if ((unsigned)gy < 128u && (unsigned)gx < 128u) {
                int   o   = gy * 128 + gx;
                int   dyo = (gy < 127) ? 128 : -128;
                float ey  = (gy < 127) ? 1.f : -1.f;

                float4 uc = *(const float4*)(pu + o);
                float4 uz = *(const float4*)(pu + o + dzo);
                float4 uy = *(const float4*)(pu + o + dyo);
                float4 vc = *(const float4*)(pv + o);
                float4 vz = *(const float4*)(pv + o + dzo);
                float4 wc = *(const float4*)(pw + o);
                float4 wy = *(const float4*)(pw + o + dyo);
                float vn4 = 0.f, wn4 = 0.f;
                if (gx + 4 < 128) { vn4 = pv[o + 4]; wn4 = pw[o + 4]; }

                // z-derivatives
                float duz0 = ez * (uz.x - uc.x), duz1 = ez * (uz.y - uc.y);
                float duz2 = ez * (uz.z - uc.z), duz3 = ez * (uz.w - uc.w);
                float dvz0 = ez * (vz.x - vc.x), dvz1 = ez * (vz.y - vc.y);
                float dvz2 = ez * (vz.z - vc.z), dvz3 = ez * (vz.w - vc.w);
                // y-derivatives
                float duy0 = ey * (uy.x - uc.x), duy1 = ey * (uy.y - uc.y);
                float duy2 = ey * (uy.z - uc.z), duy3 = ey * (uy.w - uc.w);
                float dwy0 = ey * (wy.x - wc.x), dwy1 = ey * (wy.y - wc.y);
                float dwy2 = ey * (wy.z - wc.z), dwy3 = ey * (wy.w - wc.w);
                // x-derivatives (quad-internal; .w uses neighbor or clamp)
                float dvx0 = vc.y - vc.x, dvx1 = vc.z - vc.y, dvx2 = vc.w - vc.z;
                float dwx0 = wc.y - wc.x, dwx1 = wc.z - wc.y, dwx2 = wc.w - wc.z;
                float dvx3, dwx3;
                if (gx + 3 < 127) { dvx3 = vn4 - vc.w;  dwx3 = wn4 - wc.w; }
                else              { dvx3 = vc.w - vc.z; dwx3 = wc.w - wc.z; }

                float cu0 = dwy0 - dvz0, cv0 = duz0 - dwx0, cw0 = dvx0 - duy0;
                float cu1 = dwy1 - dvz1, cv1 = duz1 - dwx1, cw1 = dvx1 - duy1;
                float cu2 = dwy2 - dvz2, cv2 = duz2 - dwx2, cw2 = dvx2 - duy2;
                float cu3 = dwy3 - dvz3, cv3 = duz3 - dwx3, cw3 = dvx3 - duy3;
                val.x = sqrtf(cu0 * cu0 + cv0 * cv0 + cw0 * cw0);
                val.y = sqrtf(cu1 * cu1 + cv1 * cv1 + cw1 * cw1);
                val.z = sqrtf(cu2 * cu2 + cv2 * cv2 + cw2 * cw2);
                val.w = sqrtf(cu3 * cu3 + cv3 * cv3 + cw3 * cw3);
            }
            *(float4*)&s_in[ly][q * 4] = val;   // lx = gx + 4
        }
    }
    __syncthreads();   // orders A y-pass s_tmp reads & B halo s_in writes

    // B x-pass: s_in lx = gx+4, so output quad ox reads lx = ox, ox+4, ox+8
    for (int i = tid; i < LDY * 32; i += 256) {
        int ly = i >> 5, ox = (i & 31) * 4;
        float4 a = *(const float4*)&s_in[ly][ox];
        float4 b = *(const float4*)&s_in[ly][ox + 4];
        float4 c = *(const float4*)&s_in[ly][ox + 8];
        *(float4*)&s_tmp[ly][ox] = xconv(a, b, c);
    }
    __syncthreads();

    ypass_store(s_tmp, g_b + (size_t)n * VOL + z * S2D, ty0, tid);
}

// ---------------------------------------------------------------------------
// Integrate kernel: fused Z-smooth + flip + cumsum + transform + trapezoid
// + clip. 512 threads = 32 columns x 16 chunks of 8 zf-steps.
// Stages fp16 -> float smem (compute path unchanged); phase 1 keeps its 8
// smoothed-ds values in registers; phase 2 replays dss[] (B-side only).
// ---------------------------------------------------------------------------
__global__ __launch_bounds__(512)
void integrate_kernel(float* __restrict__ out) {
    __shared__ float sA[128][32];
    __shared__ float sB[128][32];
    __shared__ float s_sum[16][32];
    __shared__ float s_iv [16][32];

    int tid   = threadIdx.x;
    int cl    = tid & 31;                    // column within block
    int chunk = tid >> 5;                    // 0..15 (one warp per chunk)

    int colg0 = blockIdx.x * 32;
    int n   = colg0 >> 14;
    int yx0 = colg0 & 16383;                 // 16384 % 32 == 0: no n straddle

    const __half* Abase = g_a + (size_t)n * VOL + yx0;
    const __half* Bbase = g_b + (size_t)n * VOL + yx0;

    // ---------------- Phase 0: stage columns (fp16 -> f32 smem) ----------
    for (int i = tid; i < 128 * 4; i += 512) {      // 4 x 8-half loads per z-row
        int z = i >> 2, c8 = (i & 3) * 8;
        uint4 ra = *(const uint4*)(Abase + z * S2D + c8);
        uint4 rb = *(const uint4*)(Bbase + z * S2D + c8);
        const __half2* ha = (const __half2*)&ra;
        const __half2* hb = (const __half2*)&rb;
#pragma unroll
        for (int k = 0; k < 4; k++) {
            float2 fa = __half22float2(ha[k]);
            float2 fb = __half22float2(hb[k]);
            sA[z][c8 + 2*k]     = fa.x;
            sA[z][c8 + 2*k + 1] = fa.y;
            sB[z][c8 + 2*k]     = fb.x;
            sB[z][c8 + 2*k + 1] = fb.y;
        }
    }
    __syncthreads();

    const int z0 = 127 - 8 * chunk;          // first z of this chunk (walk down)

    // ---------------- Phase 1: smoothed ds values (kept in registers) -----
    float dss[8];
    float S = 0.f;
    {
        float a[7];
#pragma unroll
        for (int k = 0; k < 7; k++) {
            int zi = z0 + k - 3;
            a[k] = ((unsigned)zi < 128u) ? sA[zi][cl] : 0.f;
        }
        int z = z0;
#pragma unroll
        for (int i = 0; i < 8; i++) {
            int pz = z - 4;
            float na = (pz >= 0) ? sA[pz][cl] : 0.f;
            float ds = W0 * a[3] + W1 * (a[2] + a[4])
                     + W2 * (a[1] + a[5]) + W3 * (a[0] + a[6]);
            dss[i] = ds;
            S += ds;
#pragma unroll
            for (int k = 6; k >= 1; k--) a[k] = a[k - 1];
            a[0] = na;
            z--;
        }
    }
    s_sum[chunk][cl] = S;
    __syncthreads();

    float Xoff = 0.f;
#pragma unroll
    for (int c = 0; c < 15; c++)
        if (c < chunk) Xoff += s_sum[c][cl];

    // ---------------- Boundary state for chunk > 0 ------------------------
    float tprev = 0.f, vprev = 0.f;
    if (chunk > 0) {
        int zb = z0 + 1;   // z at zf = 8*chunk - 1; taps all in [0,127]
        vprev = W0 * sB[zb][cl]
              + W1 * (sB[zb - 1][cl] + sB[zb + 1][cl])
              + W2 * (sB[zb - 2][cl] + sB[zb + 2][cl])
              + W3 * (sB[zb - 3][cl] + sB[zb + 3][cl]);
        tprev = (Xoff * 20.f + 1.f) * __expf(-20.f * Xoff);
    }

    // ---------------- Phase 2: B-side only (A replayed from dss[]) --------
    float b[7];
#pragma unroll
    for (int k = 0; k < 7; k++) {
        int zi = z0 + k - 3;
        b[k] = ((unsigned)zi < 128u) ? sB[zi][cl] : 0.f;
    }

    float xacc = Xoff, iv = 0.f;
    int z = z0;
#pragma unroll
    for (int i = 0; i < 8; i++) {
        int pz = z - 4;
        float nb = (pz >= 0) ? sB[pz][cl] : 0.f;

        float vn_s = W0 * b[3] + W1 * (b[2] + b[4])
                   + W2 * (b[1] + b[5]) + W3 * (b[0] + b[6]);

        xacc += dss[i];
        float tt = (xacc * 20.f + 1.f) * __expf(-20.f * xacc);

        if (i == 0 && chunk == 0)
            iv = (1.f - tt) * vn_s;                       // front term
        else
            iv += (tprev - tt) * (vprev + vn_s) * 0.5f;   // trapezoid
        tprev = tt; vprev = vn_s;

#pragma unroll
        for (int k = 6; k >= 1; k--) b[k] = b[k - 1];
        b[0] = nb;
        z--;
    }

    s_iv[chunk][cl] = iv;
    __syncthreads();

    if (chunk == 0) {
        float tot = iv;
#pragma unroll
        for (int c = 1; c < 16; c++) tot += s_iv[c][cl];
        out[colg0 + cl] = fminf(fmaxf(tot, 0.f), 1.f);
    }
}

// ---------------------------------------------------------------------------
extern "C" void kernel_launch(void* const* d_in, const int* in_sizes, int n_in,
                              void* d_out, int out_size) {
    const float* d = (const float*)d_in[0];
    const float* v = (const float*)d_in[1];
    if (in_sizes[0] > in_sizes[1]) {   // safety: d is the smaller tensor
        const float* tmp = d; d = v; v = tmp;
    }
    float* out = (float*)d_out;

    dim3 g2(128 / TSY, NB * 128);             // (y-tile, n*z)
    fused_smooth_kernel<<<g2, 256>>>(d, v);   // g_a (d) and g_b (|curl v|)

    integrate_kernel<<<65536 / 32, 512>>>(out);
}

// round 16
// speedup vs baseline: 1.0555x; 1.0555x over previous
#include <cuda_runtime.h>
#include <math.h>

#define VOL   2097152              // 128^3
#define NB    4
#define S2D   16384                // 128*128 (z stride)

// Normalized 1-D Gaussian weights (sigma=1.6, 7 taps), sum = 1.
#define W0 0.25603832f   // center
#define W1 0.21061137f   // +-1
#define W2 0.11722290f   // +-2
#define W3 0.04414655f   // +-3

// Scratch (allocation-free contract: __device__ globals)
__device__ float g_a [(size_t)NB * VOL];   // d   smoothed in x,y
__device__ float g_b [(size_t)NB * VOL];   // |curl v| smoothed in x,y

#define TSY 16
#define LDY 22    // TSY + 6 (y halo rows)
#define NQB 34    // phase-B halo quads per row: gx in [-4, 132)
#define SIN 140   // s_in row stride (floats): 136 data + 4 pad (560B, 16B mult)
#define NYS (TSY / 4)        // y strips in y-pass
#define NIT (NYS * 32)       // y-pass items (strip x quad)

#define F4Z make_float4(0.f, 0.f, 0.f, 0.f)

// 7-tap x-conv of a 4-wide output quad from three f4 windows:
// a = values at ox-4.., b = ox.., c = ox+4..
__device__ __forceinline__ float4 xconv(float4 a, float4 b, float4 c) {
    float4 r;
    r.x = W0 * b.x + W1 * (a.w + b.y) + W2 * (a.z + b.z) + W3 * (a.y + b.w);
    r.y = W0 * b.y + W1 * (b.x + b.z) + W2 * (a.w + b.w) + W3 * (a.z + c.x);
    r.z = W0 * b.z + W1 * (b.y + b.w) + W2 * (b.x + c.x) + W3 * (a.w + c.y);
    r.w = W0 * b.w + W1 * (b.z + c.x) + W2 * (b.y + c.y) + W3 * (b.x + c.z);
    return r;
}

// y-pass: one output quad column x 4 rows from a 10-row register window.
// itm in [0,NIT): ox = (itm&31)*4, oy = (itm>>5)*4.
__device__ __forceinline__ void ypass_store(const float (*s_tmp)[128],
                                            float* outp, int ty0, int itm) {
    int ox = (itm & 31) * 4;
    int oy = (itm >> 5) * 4;
    float4 t[10];
#pragma unroll
    for (int r = 0; r < 10; r++)
        t[r] = *(const float4*)&s_tmp[oy + r][ox];
#pragma unroll
    for (int j = 0; j < 4; j++) {
        float4 r4;
        r4.x = W0 * t[j+3].x + W1 * (t[j+2].x + t[j+4].x)
             + W2 * (t[j+1].x + t[j+5].x) + W3 * (t[j].x + t[j+6].x);
        r4.y = W0 * t[j+3].y + W1 * (t[j+2].y + t[j+4].y)
             + W2 * (t[j+1].y + t[j+5].y) + W3 * (t[j].y + t[j+6].y);
        r4.z = W0 * t[j+3].z + W1 * (t[j+2].z + t[j+4].z)
             + W2 * (t[j+1].z + t[j+5].z) + W3 * (t[j].z + t[j+6].z);
        r4.w = W0 * t[j+3].w + W1 * (t[j+2].w + t[j+4].w)
             + W2 * (t[j+1].w + t[j+5].w) + W3 * (t[j].w + t[j+6].w);
        *(float4*)(outp + (ty0 + oy + j) * 128 + ox) = r4;
    }
}

// ---------------------------------------------------------------------------
// Fused kernel, full-width 128x16 tiles (4096 blocks -> ~7 resident/SM):
//   phase A: d -> x-conv DIRECTLY from global (no staging) -> s_tmp -> y-pass -> g_a
//   phase B: |curl v| halo -> s_in -> x-pass -> s_tmp -> y-pass -> g_b
// fdiff clamp via diff = e*(f[o+delta]-f[o]) with (delta,e) flipped at i==127.
// Convolution zero-pads outside the 128x128 slice.
// ---------------------------------------------------------------------------
__global__ __launch_bounds__(256)
void fused_smooth_kernel(const float* __restrict__ d,
                         const float* __restrict__ v) {
    int ty0 = blockIdx.x * TSY;
    int nz  = blockIdx.y;            // n*128 + z
    int n = nz >> 7, z = nz & 127;

    __shared__ __align__(16) float s_in [LDY][SIN];
    __shared__ __align__(16) float s_tmp[LDY][128];

    int tid = threadIdx.x;

    // ============ phase A : x-conv of d straight from global =============
    {
        const float* slice = d + (size_t)n * VOL + z * S2D;
        for (int i = tid; i < LDY * 32; i += 256) {
            int ly = i >> 5, qx = i & 31;
            int gy = ty0 + ly - 3, ox = qx * 4;
            float4 a = F4Z, b = F4Z, c = F4Z;
            if ((unsigned)gy < 128u) {
                const float* row = slice + gy * 128;
                if (qx >= 1)  a = *(const float4*)(row + ox - 4);
                b = *(const float4*)(row + ox);
                if (qx <= 30) c = *(const float4*)(row + ox + 4);
            }
            *(float4*)&s_tmp[ly][ox] = xconv(a, b, c);
        }
    }
    __syncthreads();

    // A y-pass (reads s_tmp only) — overlaps with phase-B halo (writes s_in)
    if (tid < NIT)
        ypass_store(s_tmp, g_a + (size_t)n * VOL + z * S2D, ty0, tid);

    // ======================= phase B : |curl v| halo ======================
    {
        const float* pu = v + (size_t)(n * 3 + 0) * VOL + z * S2D;
        const float* pv = v + (size_t)(n * 3 + 1) * VOL + z * S2D;
        const float* pw = v + (size_t)(n * 3 + 2) * VOL + z * S2D;
        const int   dzo = (z < 127) ? S2D : -S2D;
        const float ez  = (z < 127) ? 1.f : -1.f;

        for (int i = tid; i < LDY * NQB; i += 256) {
            int ly = i / NQB, q = i - ly * NQB;
            int gy = ty0 + ly - 3, gx = q * 4 - 4;
            float4 val = F4Z;
            if ((unsigned)gy < 128u && (unsigned)gx < 128u) {
                int   o   = gy * 128 + gx;
                int   dyo = (gy < 127) ? 128 : -128;
                float ey  = (gy < 127) ? 1.f : -1.f;

                float4 uc = *(const float4*)(pu + o);
                float4 uz = *(const float4*)(pu + o + dzo);
                float4 uy = *(const float4*)(pu + o + dyo);
                float4 vc = *(const float4*)(pv + o);
                float4 vz = *(const float4*)(pv + o + dzo);
                float4 wc = *(const float4*)(pw + o);
                float4 wy = *(const float4*)(pw + o + dyo);
                float vn4 = 0.f, wn4 = 0.f;
                if (gx + 4 < 128) { vn4 = pv[o + 4]; wn4 = pw[o + 4]; }

                // z-derivatives
                float duz0 = ez * (uz.x - uc.x), duz1 = ez * (uz.y - uc.y);
                float duz2 = ez * (uz.z - uc.z), duz3 = ez * (uz.w - uc.w);
                float dvz0 = ez * (vz.x - vc.x), dvz1 = ez * (vz.y - vc.y);
                float dvz2 = ez * (vz.z - vc.z), dvz3 = ez * (vz.w - vc.w);
                // y-derivatives
                float duy0 = ey * (uy.x - uc.x), duy1 = ey * (uy.y - uc.y);
                float duy2 = ey * (uy.z - uc.z), duy3 = ey * (uy.w - uc.w);
                float dwy0 = ey * (wy.x - wc.x), dwy1 = ey * (wy.y - wc.y);
                float dwy2 = ey * (wy.z - wc.z), dwy3 = ey * (wy.w - wc.w);
                // x-derivatives (quad-internal; .w uses neighbor or clamp)
                float dvx0 = vc.y - vc.x, dvx1 = vc.z - vc.y, dvx2 = vc.w - vc.z;
                float dwx0 = wc.y - wc.x, dwx1 = wc.z - wc.y, dwx2 = wc.w - wc.z;
                float dvx3, dwx3;
                if (gx + 3 < 127) { dvx3 = vn4 - vc.w;  dwx3 = wn4 - wc.w; }
                else              { dvx3 = vc.w - vc.z; dwx3 = wc.w - wc.z; }

                float cu0 = dwy0 - dvz0, cv0 = duz0 - dwx0, cw0 = dvx0 - duy0;
                float cu1 = dwy1 - dvz1, cv1 = duz1 - dwx1, cw1 = dvx1 - duy1;
                float cu2 = dwy2 - dvz2, cv2 = duz2 - dwx2, cw2 = dvx2 - duy2;
                float cu3 = dwy3 - dvz3, cv3 = duz3 - dwx3, cw3 = dvx3 - duy3;
                val.x = sqrtf(cu0 * cu0 + cv0 * cv0 + cw0 * cw0);
                val.y = sqrtf(cu1 * cu1 + cv1 * cv1 + cw1 * cw1);
                val.z = sqrtf(cu2 * cu2 + cv2 * cv2 + cw2 * cw2);
                val.w = sqrtf(cu3 * cu3 + cv3 * cv3 + cw3 * cw3);
            }
            *(float4*)&s_in[ly][q * 4] = val;   // lx = gx + 4
        }
    }
    __syncthreads();   // orders A y-pass s_tmp reads & B halo s_in writes

    // B x-pass: s_in lx = gx+4, so output quad ox reads lx = ox, ox+4, ox+8
    for (int i = tid; i < LDY * 32; i += 256) {
        int ly = i >> 5, ox = (i & 31) * 4;
        float4 a = *(const float4*)&s_in[ly][ox];
        float4 b = *(const float4*)&s_in[ly][ox + 4];
        float4 c = *(const float4*)&s_in[ly][ox + 8];
        *(float4*)&s_tmp[ly][ox] = xconv(a, b, c);
    }
    __syncthreads();

    if (tid < NIT)
        ypass_store(s_tmp, g_b + (size_t)n * VOL + z * S2D, ty0, tid);
}

// ---------------------------------------------------------------------------
// Integrate kernel (R13 version — 23.5us, protected).
// 512 threads = 32 columns x 16 chunks of 8 zf-steps; fp32 staging; phase 1
// keeps smoothed-ds in registers, phase 2 replays dss[] (B-side only).
// ---------------------------------------------------------------------------
__global__ __launch_bounds__(512)
void integrate_kernel(float* __restrict__ out) {
    __shared__ float sA[128][32];
    __shared__ float sB[128][32];
    __shared__ float s_sum[16][32];
    __shared__ float s_iv [16][32];

    int tid   = threadIdx.x;
    int cl    = tid & 31;                    // column within block
    int chunk = tid >> 5;                    // 0..15 (one warp per chunk)

    int colg0 = blockIdx.x * 32;
    int n   = colg0 >> 14;
    int yx0 = colg0 & 16383;                 // 16384 % 32 == 0: no n straddle

    const float* Abase = g_a + (size_t)n * VOL + yx0;
    const float* Bbase = g_b + (size_t)n * VOL + yx0;

    // ---------------- Phase 0: stage columns ------------------------------
    for (int i = tid; i < 128 * 8; i += 512) {      // 8 float4 per z-row
        int z = i >> 3, c4 = (i & 7) << 2;
        *(float4*)&sA[z][c4] = *(const float4*)(Abase + z * S2D + c4);
        *(float4*)&sB[z][c4] = *(const float4*)(Bbase + z * S2D + c4);
    }
    __syncthreads();

    const int z0 = 127 - 8 * chunk;          // first z of this chunk (walk down)

    // ---------------- Phase 1: smoothed ds values (kept in registers) -----
    float dss[8];
    float S = 0.f;
    {
        float a[7];
#pragma unroll
        for (int k = 0; k < 7; k++) {
            int zi = z0 + k - 3;
            a[k] = ((unsigned)zi < 128u) ? sA[zi][cl] : 0.f;
        }
        int z = z0;
#pragma unroll
        for (int i = 0; i < 8; i++) {
            int pz = z - 4;
            float na = (pz >= 0) ? sA[pz][cl] : 0.f;
            float ds = W0 * a[3] + W1 * (a[2] + a[4])
                     + W2 * (a[1] + a[5]) + W3 * (a[0] + a[6]);
            dss[i] = ds;
            S += ds;
#pragma unroll
            for (int k = 6; k >= 1; k--) a[k] = a[k - 1];
            a[0] = na;
            z--;
        }
    }
    s_sum[chunk][cl] = S;
    __syncthreads();

    float Xoff = 0.f;
#pragma unroll
    for (int c = 0; c < 15; c++)
        if (c < chunk) Xoff += s_sum[c][cl];

    // ---------------- Boundary state for chunk > 0 ------------------------
    float tprev = 0.f, vprev = 0.f;
    if (chunk > 0) {
        int zb = z0 + 1;   // z at zf = 8*chunk - 1; taps all in [0,127]
        vprev = W0 * sB[zb][cl]
              + W1 * (sB[zb - 1][cl] + sB[zb + 1][cl])
              + W2 * (sB[zb - 2][cl] + sB[zb + 2][cl])
              + W3 * (sB[zb - 3][cl] + sB[zb + 3][cl]);
        tprev = (Xoff * 20.f + 1.f) * __expf(-20.f * Xoff);
    }

    // ---------------- Phase 2: B-side only (A replayed from dss[]) --------
    float b[7];
#pragma unroll
    for (int k = 0; k < 7; k++) {
        int zi = z0 + k - 3;
        b[k] = ((unsigned)zi < 128u) ? sB[zi][cl] : 0.f;
    }

    float xacc = Xoff, iv = 0.f;
    int z = z0;
#pragma unroll
    for (int i = 0; i < 8; i++) {
        int pz = z - 4;
        float nb = (pz >= 0) ? sB[pz][cl] : 0.f;

        float vn_s = W0 * b[3] + W1 * (b[2] + b[4])
                   + W2 * (b[1] + b[5]) + W3 * (b[0] + b[6]);

        xacc += dss[i];
        float tt = (xacc * 20.f + 1.f) * __expf(-20.f * xacc);

        if (i == 0 && chunk == 0)
            iv = (1.f - tt) * vn_s;                       // front term
        else
            iv += (tprev - tt) * (vprev + vn_s) * 0.5f;   // trapezoid
        tprev = tt; vprev = vn_s;

#pragma unroll
        for (int k = 6; k >= 1; k--) b[k] = b[k - 1];
        b[0] = nb;
        z--;
    }

    s_iv[chunk][cl] = iv;
    __syncthreads();

    if (chunk == 0) {
        float tot = iv;
#pragma unroll
        for (int c = 1; c < 16; c++) tot += s_iv[c][cl];
        out[colg0 + cl] = fminf(fmaxf(tot, 0.f), 1.f);
    }
}

// ---------------------------------------------------------------------------
extern "C" void kernel_launch(void* const* d_in, const int* in_sizes, int n_in,
                              void* d_out, int out_size) {
    const float* d = (const float*)d_in[0];
    const float* v = (const float*)d_in[1];
    if (in_sizes[0] > in_sizes[1]) {   // safety: d is the smaller tensor
        const float* tmp = d; d = v; v = tmp;
    }
    float* out = (float*)d_out;

    dim3 g2(128 / TSY, NB * 128);             // (y-tile, n*z)
    fused_smooth_kernel<<<g2, 256>>>(d, v);   // g_a (d) and g_b (|curl v|)

    integrate_kernel<<<65536 / 32, 512>>>(out);
}